// round 16
// baseline (speedup 1.0000x reference)
#include <cuda_runtime.h>
#include <cuda_fp16.h>

// Problem constants (fixed by the reference)
#define N_NODES 20000
#define N_EDGES 200000
#define N_SEG   16
#define EXTENT  32
#define N_PATHS 64
#define OP_SIZE (N_SEG * EXTENT)   // 512
#define EPB     8                  // edges per group
#define GPB     2                  // groups per block (pipelined)
#define OUT_ELEMS (N_NODES * OP_SIZE)
#define XN_ELEMS  (N_NODES * OP_SIZE)   // 10.24M halves = 20.5 MB

// Path metadata sorted by output segment (i3), built by prep kernel.
__device__ int4 g_meta[N_PATHS];
__device__ int  g_seg_start[N_SEG + 1];

// f16 copy of x_nodes (static device scratch — no runtime allocation).
__device__ __half g_xnodes_h[XN_ELEMS];

// Prep: grid-stride zero of out (harness poisons it) + single-thread path sort.
__global__ void prep_kernel(const int* __restrict__ path_indices,
                            const float* __restrict__ path_coeffs,
                            float4* __restrict__ out4) {
    const int i = blockIdx.x * blockDim.x + threadIdx.x;
    const int stride = gridDim.x * blockDim.x;
    for (int k = i; k < OUT_ELEMS / 4; k += stride)
        out4[k] = make_float4(0.f, 0.f, 0.f, 0.f);

    if (blockIdx.x == 0 && threadIdx.x == 0) {
        int cnt[N_SEG];
#pragma unroll
        for (int s = 0; s < N_SEG; s++) cnt[s] = 0;
        for (int p = 0; p < N_PATHS; p++) cnt[path_indices[p * 3 + 2]]++;
        int start[N_SEG + 1];
        start[0] = 0;
#pragma unroll
        for (int s = 0; s < N_SEG; s++) start[s + 1] = start[s] + cnt[s];
        for (int s = 0; s <= N_SEG; s++) g_seg_start[s] = start[s];
        int pos[N_SEG];
#pragma unroll
        for (int s = 0; s < N_SEG; s++) pos[s] = start[s];
        for (int p = 0; p < N_PATHS; p++) {
            int s   = path_indices[p * 3 + 2];
            int idx = pos[s]++;
            int4 m;
            m.x = path_indices[p * 3 + 0] * (EXTENT * EPB * 2);  // bytes
            m.y = path_indices[p * 3 + 1] * (EXTENT * EPB * 2);
            m.z = __float_as_int(path_coeffs[p]);
            m.w = 0;
            g_meta[idx] = m;
        }
    }
}

// Pre-convert x_nodes f32 -> f16 (rn, identical rounding to the old in-kernel
// cvt, so results are bit-identical). Grid-stride, float4 -> 2x half2.
__global__ void convert_xnodes_kernel(const float4* __restrict__ xn4) {
    const int i = blockIdx.x * blockDim.x + threadIdx.x;
    const int stride = gridDim.x * blockDim.x;
    uint2* dst = (uint2*)g_xnodes_h;
    for (int k = i; k < XN_ELEMS / 4; k += stride) {
        const float4 v = xn4[k];
        __half2 lo = __floats2half2_rn(v.x, v.y);
        __half2 hi = __floats2half2_rn(v.z, v.w);
        uint2 pk;
        pk.x = *(const unsigned*)&lo;
        pk.y = *(const unsigned*)&hi;
        dst[k] = pk;
    }
}

// Stage one 8-edge group into the given f16 tile pair ([pos][edge] transposed).
__device__ __forceinline__ void stage_group(const float* __restrict__ x_edges,
                                            const int* __restrict__ src,
                                            int e0, int t,
                                            __half* s_x1, __half* s_x2) {
    // x_edges: thread t owns position t; gather from 8 edges (MLP 8), evict-first.
    {
        const float* base = x_edges + (size_t)e0 * OP_SIZE + t;
        float v[EPB];
#pragma unroll
        for (int k = 0; k < EPB; k++)
            v[k] = __ldcs(base + k * OP_SIZE);
        __half2 h0 = __floats2half2_rn(v[0], v[1]);
        __half2 h1 = __floats2half2_rn(v[2], v[3]);
        __half2 h2 = __floats2half2_rn(v[4], v[5]);
        __half2 h3 = __floats2half2_rn(v[6], v[7]);
        uint4 pk;
        pk.x = *(const unsigned*)&h0; pk.y = *(const unsigned*)&h1;
        pk.z = *(const unsigned*)&h2; pk.w = *(const unsigned*)&h3;
        ((uint4*)s_x2)[t] = pk;   // addr = t*16 -> conflict-free
    }
    // x_nodes rows src[e0..e0+7], already f16: LDG.16 (half the bytes) and
    // pure register packing (no cvt). 32-bit offsets (20.5MB fits unsigned).
    {
        __half h[EPB];
#pragma unroll
        for (int e = 0; e < EPB; e++) {
            const unsigned r = (unsigned)src[e0 + e] * (unsigned)OP_SIZE + (unsigned)t;
            h[e] = g_xnodes_h[r];
        }
        __half2 h0 = __halves2half2(h[0], h[1]);
        __half2 h1 = __halves2half2(h[2], h[3]);
        __half2 h2 = __halves2half2(h[4], h[5]);
        __half2 h3 = __halves2half2(h[6], h[7]);
        uint4 pk;
        pk.x = *(const unsigned*)&h0; pk.y = *(const unsigned*)&h1;
        pk.z = *(const unsigned*)&h2; pk.w = *(const unsigned*)&h3;
        ((uint4*)s_x1)[t] = pk;
    }
}

// One path-contraction step over 8 edges.
__device__ __forceinline__ void path_step(const int4 m,
                                          const char* b1, const char* b2,
                                          float* a) {
    const float c = __int_as_float(m.z);
    const uint4 w1 = *(const uint4*)(b1 + m.x);     // LDS.128: 8 edges (x1)
    const uint4 w2 = *(const uint4*)(b2 + m.y);     // LDS.128: 8 edges (x2)
    const __half2 p0 = __hmul2(*(const __half2*)&w1.x, *(const __half2*)&w2.x);
    const __half2 p1 = __hmul2(*(const __half2*)&w1.y, *(const __half2*)&w2.y);
    const __half2 p2 = __hmul2(*(const __half2*)&w1.z, *(const __half2*)&w2.z);
    const __half2 p3 = __hmul2(*(const __half2*)&w1.w, *(const __half2*)&w2.w);
    const float2 f0 = __half22float2(p0);
    const float2 f1 = __half22float2(p1);
    const float2 f2 = __half22float2(p2);
    const float2 f3 = __half22float2(p3);
    a[0] = fmaf(c, f0.x, a[0]);  a[1] = fmaf(c, f0.y, a[1]);
    a[2] = fmaf(c, f1.x, a[2]);  a[3] = fmaf(c, f1.y, a[3]);
    a[4] = fmaf(c, f2.x, a[4]);  a[5] = fmaf(c, f2.y, a[5]);
    a[6] = fmaf(c, f3.x, a[6]);  a[7] = fmaf(c, f3.y, a[7]);
}

// Two pipelined 8-edge groups per block, double-buffered f16 tiles.
__global__ __launch_bounds__(OP_SIZE, 4)
void seg_poly_kernel(const float* __restrict__ x_edges,
                     const int* __restrict__ src,
                     const int* __restrict__ dst,
                     float* __restrict__ out) {
    __shared__ __align__(16) __half s_x1[GPB][OP_SIZE * EPB];  // 2 x 8 KB
    __shared__ __align__(16) __half s_x2[GPB][OP_SIZE * EPB];  // 2 x 8 KB
    __shared__ int4 s_meta[N_PATHS];
    __shared__ int  s_start[N_SEG + 1];
    __shared__ int  s_dst[GPB][EPB];

    const int e0 = blockIdx.x * (GPB * EPB);
    const int t  = threadIdx.x;

    stage_group(x_edges, src, e0, t, s_x1[0], s_x2[0]);

    if (t < N_PATHS) s_meta[t] = g_meta[t];
    if (t <= N_SEG)  s_start[t] = g_seg_start[t];
    if (t < GPB * EPB) s_dst[t / EPB][t % EPB] = dst[e0 + t];
    __syncthreads();

    const int lane = t & 31;
    const int j0 = s_start[t >> 5];
    const int j1 = s_start[(t >> 5) + 1];
    const int loff = lane * (EPB * 2);

#pragma unroll
    for (int g = 0; g < GPB; g++) {
        const char* b1 = (const char*)s_x1[g] + loff;
        const char* b2 = (const char*)s_x2[g] + loff;

        float a[EPB];
#pragma unroll
        for (int k = 0; k < EPB; k++) a[k] = 0.f;

        // Guarded unroll-4 (most segments have <=4 paths) + rare spill.
#pragma unroll
        for (int u = 0; u < 4; u++) {
            const int j = j0 + u;
            if (j < j1) path_step(s_meta[j], b1, b2, a);
        }
        for (int j = j0 + 4; j < j1; j++) path_step(s_meta[j], b1, b2, a);

        if (j1 > j0) {
            // Unused return -> no-return reduction, coalesced 128B per warp.
            float* obase = out + t;
#pragma unroll
            for (int k = 0; k < EPB; k++)
                atomicAdd(obase + (unsigned)s_dst[g][k] * (unsigned)OP_SIZE, a[k]);
        }

        if (g + 1 < GPB) {
            // Pre-barrier staging of the next group into the other buffer.
            stage_group(x_edges, src, e0 + (g + 1) * EPB, t,
                        s_x1[g + 1], s_x2[g + 1]);
            __syncthreads();
        }
    }
    // Segments with no paths contribute exactly 0 -> output stays zeroed.
}

extern "C" void kernel_launch(void* const* d_in, const int* in_sizes, int n_in,
                              void* d_out, int out_size) {
    const float* x_nodes      = (const float*)d_in[0];
    const float* x_edges      = (const float*)d_in[1];
    const float* path_coeffs  = (const float*)d_in[2];
    const int*   src          = (const int*)d_in[3];
    const int*   dst          = (const int*)d_in[4];
    const int*   path_indices = (const int*)d_in[5];
    float* out = (float*)d_out;

    // Zero the poisoned output + build path metadata.
    prep_kernel<<<2048, 256>>>(path_indices, path_coeffs, (float4*)out);
    // One-time f32 -> f16 conversion of x_nodes (identical rounding to before).
    convert_xnodes_kernel<<<2048, 256>>>((const float4*)x_nodes);

    seg_poly_kernel<<<N_EDGES / (GPB * EPB), OP_SIZE>>>(x_edges, src, dst, out);
}

// round 17
// speedup vs baseline: 1.0318x; 1.0318x over previous
#include <cuda_runtime.h>
#include <cuda_fp16.h>

// Problem constants (fixed by the reference)
#define N_NODES 20000
#define N_EDGES 200000
#define N_SEG   16
#define EXTENT  32
#define N_PATHS 64
#define OP_SIZE (N_SEG * EXTENT)   // 512
#define EPB     8                  // edges per group
#define GPB     2                  // groups per block
#define OUT_ELEMS (N_NODES * OP_SIZE)

// Path metadata sorted by output segment (i3), built by prep kernel.
// meta.x = i1 tile byte offset in half[pos][EPB] layout (= i1*EXTENT*EPB*2)
// meta.y = i2 tile byte offset, meta.z = coeff bits (f32).
__device__ int4 g_meta[N_PATHS];
__device__ int  g_seg_start[N_SEG + 1];

// Prep: grid-stride zero of out (harness poisons it) + single-thread path sort.
__global__ void prep_kernel(const int* __restrict__ path_indices,
                            const float* __restrict__ path_coeffs,
                            float4* __restrict__ out4) {
    const int i = blockIdx.x * blockDim.x + threadIdx.x;
    const int stride = gridDim.x * blockDim.x;
    for (int k = i; k < OUT_ELEMS / 4; k += stride)
        out4[k] = make_float4(0.f, 0.f, 0.f, 0.f);

    if (blockIdx.x == 0 && threadIdx.x == 0) {
        int cnt[N_SEG];
#pragma unroll
        for (int s = 0; s < N_SEG; s++) cnt[s] = 0;
        for (int p = 0; p < N_PATHS; p++) cnt[path_indices[p * 3 + 2]]++;
        int start[N_SEG + 1];
        start[0] = 0;
#pragma unroll
        for (int s = 0; s < N_SEG; s++) start[s + 1] = start[s] + cnt[s];
        for (int s = 0; s <= N_SEG; s++) g_seg_start[s] = start[s];
        int pos[N_SEG];
#pragma unroll
        for (int s = 0; s < N_SEG; s++) pos[s] = start[s];
        for (int p = 0; p < N_PATHS; p++) {
            int s   = path_indices[p * 3 + 2];
            int idx = pos[s]++;
            int4 m;
            m.x = path_indices[p * 3 + 0] * (EXTENT * EPB * 2);  // bytes
            m.y = path_indices[p * 3 + 1] * (EXTENT * EPB * 2);
            m.z = __float_as_int(path_coeffs[p]);
            m.w = 0;
            g_meta[idx] = m;
        }
    }
}

// Stage one 8-edge group into the given f16 tile pair ([pos][edge] transposed).
__device__ __forceinline__ void stage_group(const float* __restrict__ x_nodes,
                                            const float* __restrict__ x_edges,
                                            const int* __restrict__ src,
                                            int e0, int t,
                                            __half* s_x1, __half* s_x2) {
    // x_edges: thread t owns position t; gather from 8 edges (MLP 8), evict-first.
    {
        const float* base = x_edges + (size_t)e0 * OP_SIZE + t;
        float v[EPB];
#pragma unroll
        for (int k = 0; k < EPB; k++)
            v[k] = __ldcs(base + k * OP_SIZE);
        __half2 h0 = __floats2half2_rn(v[0], v[1]);
        __half2 h1 = __floats2half2_rn(v[2], v[3]);
        __half2 h2 = __floats2half2_rn(v[4], v[5]);
        __half2 h3 = __floats2half2_rn(v[6], v[7]);
        uint4 pk;
        pk.x = *(const unsigned*)&h0; pk.y = *(const unsigned*)&h1;
        pk.z = *(const unsigned*)&h2; pk.w = *(const unsigned*)&h3;
        ((uint4*)s_x2)[t] = pk;   // addr = t*16 -> conflict-free
    }
    // x_nodes rows src[e0..e0+7]; 32-bit offsets (41MB fits unsigned).
    {
        unsigned r[EPB];
#pragma unroll
        for (int e = 0; e < EPB; e++)
            r[e] = (unsigned)src[e0 + e] * (unsigned)OP_SIZE + (unsigned)t;
        float v[EPB];
#pragma unroll
        for (int e = 0; e < EPB; e++)
            v[e] = x_nodes[r[e]];
        __half2 h0 = __floats2half2_rn(v[0], v[1]);
        __half2 h1 = __floats2half2_rn(v[2], v[3]);
        __half2 h2 = __floats2half2_rn(v[4], v[5]);
        __half2 h3 = __floats2half2_rn(v[6], v[7]);
        uint4 pk;
        pk.x = *(const unsigned*)&h0; pk.y = *(const unsigned*)&h1;
        pk.z = *(const unsigned*)&h2; pk.w = *(const unsigned*)&h3;
        ((uint4*)s_x1)[t] = pk;
    }
}

// One path-contraction step over 8 edges.
__device__ __forceinline__ void path_step(const int4 m,
                                          const char* b1, const char* b2,
                                          float* a) {
    const float c = __int_as_float(m.z);
    const uint4 w1 = *(const uint4*)(b1 + m.x);     // LDS.128: 8 edges (x1)
    const uint4 w2 = *(const uint4*)(b2 + m.y);     // LDS.128: 8 edges (x2)
    const __half2 p0 = __hmul2(*(const __half2*)&w1.x, *(const __half2*)&w2.x);
    const __half2 p1 = __hmul2(*(const __half2*)&w1.y, *(const __half2*)&w2.y);
    const __half2 p2 = __hmul2(*(const __half2*)&w1.z, *(const __half2*)&w2.z);
    const __half2 p3 = __hmul2(*(const __half2*)&w1.w, *(const __half2*)&w2.w);
    const float2 f0 = __half22float2(p0);
    const float2 f1 = __half22float2(p1);
    const float2 f2 = __half22float2(p2);
    const float2 f3 = __half22float2(p3);
    a[0] = fmaf(c, f0.x, a[0]);  a[1] = fmaf(c, f0.y, a[1]);
    a[2] = fmaf(c, f1.x, a[2]);  a[3] = fmaf(c, f1.y, a[3]);
    a[4] = fmaf(c, f2.x, a[4]);  a[5] = fmaf(c, f2.y, a[5]);
    a[6] = fmaf(c, f3.x, a[6]);  a[7] = fmaf(c, f3.y, a[7]);
}

// Two 8-edge groups per block, both staged up-front (16 outstanding LDG
// chains, max MLP), then ONE barrier, then compute+atomics for both groups.
// Halves barrier count vs the pipelined form; cross-block overlap (4 blocks/SM)
// hides the staging latency of other blocks.
__global__ __launch_bounds__(OP_SIZE, 4)
void seg_poly_kernel(const float* __restrict__ x_nodes,
                     const float* __restrict__ x_edges,
                     const int* __restrict__ src,
                     const int* __restrict__ dst,
                     float* __restrict__ out) {
    __shared__ __align__(16) __half s_x1[GPB][OP_SIZE * EPB];  // 2 x 8 KB
    __shared__ __align__(16) __half s_x2[GPB][OP_SIZE * EPB];  // 2 x 8 KB
    __shared__ int4 s_meta[N_PATHS];
    __shared__ int  s_start[N_SEG + 1];
    __shared__ int  s_dst[GPB][EPB];

    const int e0 = blockIdx.x * (GPB * EPB);
    const int t  = threadIdx.x;

    // Stage BOTH groups before the single barrier.
    stage_group(x_nodes, x_edges, src, e0, t, s_x1[0], s_x2[0]);
    stage_group(x_nodes, x_edges, src, e0 + EPB, t, s_x1[1], s_x2[1]);

    if (t < N_PATHS) s_meta[t] = g_meta[t];
    if (t <= N_SEG)  s_start[t] = g_seg_start[t];
    if (t < GPB * EPB) s_dst[t / EPB][t % EPB] = dst[e0 + t];
    __syncthreads();

    const int lane = t & 31;
    const int j0 = s_start[t >> 5];
    const int j1 = s_start[(t >> 5) + 1];
    const int loff = lane * (EPB * 2);

#pragma unroll
    for (int g = 0; g < GPB; g++) {
        const char* b1 = (const char*)s_x1[g] + loff;
        const char* b2 = (const char*)s_x2[g] + loff;

        float a[EPB];
#pragma unroll
        for (int k = 0; k < EPB; k++) a[k] = 0.f;

        // Guarded unroll-4 (most segments have <=4 paths) + rare spill.
#pragma unroll
        for (int u = 0; u < 4; u++) {
            const int j = j0 + u;
            if (j < j1) path_step(s_meta[j], b1, b2, a);
        }
        for (int j = j0 + 4; j < j1; j++) path_step(s_meta[j], b1, b2, a);

        if (j1 > j0) {
            // Unused return -> no-return reduction, coalesced 128B per warp.
            float* obase = out + t;
#pragma unroll
            for (int k = 0; k < EPB; k++)
                atomicAdd(obase + (unsigned)s_dst[g][k] * (unsigned)OP_SIZE, a[k]);
        }
    }
    // Segments with no paths contribute exactly 0 -> output stays zeroed.
}

extern "C" void kernel_launch(void* const* d_in, const int* in_sizes, int n_in,
                              void* d_out, int out_size) {
    const float* x_nodes      = (const float*)d_in[0];
    const float* x_edges      = (const float*)d_in[1];
    const float* path_coeffs  = (const float*)d_in[2];
    const int*   src          = (const int*)d_in[3];
    const int*   dst          = (const int*)d_in[4];
    const int*   path_indices = (const int*)d_in[5];
    float* out = (float*)d_out;

    // Zero the poisoned output + build path metadata in one launch.
    prep_kernel<<<2048, 256>>>(path_indices, path_coeffs, (float4*)out);

    seg_poly_kernel<<<N_EDGES / (GPB * EPB), OP_SIZE>>>(x_nodes, x_edges,
                                                        src, dst, out);
}